// round 11
// baseline (speedup 1.0000x reference)
#include <cuda_runtime.h>
#include <cstdint>

// MultiHeadEMA as a chunked diagonal linear recurrence (no FFT).
// out[b,t,d] = sum_n c[d,n] * h[d,n,t] + omega[d]*x[b,t,d]
// h[t] = q*h[t-1] + x[t],  q = 1 - sigmoid(delta)*sigmoid(alpha),
// c = sigmoid(delta)*beta*gamma*sqrt(1/N)
//
// R11: x chunk tile persists in SMEM across pass1/pass2 -> x read from DRAM
// exactly once (402MB -> ~285MB traffic). C=32, CHAN=128, 64KB dynamic smem,
// 3 CTAs/SM. All 8 cp.async stages issued up front (full MLP), per-stage
// wait_group gating. Decoupled lookback as weighted sum of Le (L2-resident).

#define cB 8
#define cL 4096
#define cD 1024
#define cN 16
#define cC 32            // chunks
#define cS (cL / cC)     // 128 steps per chunk
#define TD 128           // threads per block (1 channel per thread)
#define CHAN 128         // channels per CTA
#define ST 16            // timesteps per smem stage
#define NSTAGES (cS / ST)        // 8
#define NDBLK (cD / CHAN)        // 8
#define NFLAGS (cB * cC * NDBLK) // 2048
#define SMEM_BYTES (cS * CHAN * 4)  // 65536

typedef unsigned long long u64;
typedef unsigned int u32;

// scratch (static __device__ arrays: no allocations allowed)
__device__ float g_q[cD * cN];
__device__ float g_cc[cD * cN];
__device__ float g_qS[cD * cN];
__device__ float g_Le[(size_t)cB * cC * cD * cN];  // local chunk end states
__device__ volatile int g_flag[NFLAGS];            // per (b,c,dblk) publish flag

__device__ __forceinline__ u64 pack2(float lo, float hi) {
    u64 r; asm("mov.b64 %0,{%1,%2};" : "=l"(r) : "f"(lo), "f"(hi)); return r;
}
__device__ __forceinline__ float2 unpack2(u64 v) {
    float2 f; asm("mov.b64 {%0,%1},%2;" : "=f"(f.x), "=f"(f.y) : "l"(v)); return f;
}
__device__ __forceinline__ u64 fma2(u64 a, u64 b, u64 c) {
    u64 d; asm("fma.rn.f32x2 %0,%1,%2,%3;" : "=l"(d) : "l"(a), "l"(b), "l"(c)); return d;
}
__device__ __forceinline__ u64 mul2(u64 a, u64 b) {
    u64 d; asm("mul.rn.f32x2 %0,%1,%2;" : "=l"(d) : "l"(a), "l"(b)); return d;
}
__device__ __forceinline__ u64 add2(u64 a, u64 b) {
    u64 d; asm("add.rn.f32x2 %0,%1,%2;" : "=l"(d) : "l"(a), "l"(b)); return d;
}
__device__ __forceinline__ void cp16(u32 saddr, const float* g) {
    asm volatile("cp.async.ca.shared.global [%0], [%1], 16;" :: "r"(saddr), "l"(g));
}
__device__ __forceinline__ void cp_commit() {
    asm volatile("cp.async.commit_group;");
}
// wait until <= n groups pending (n folds to an immediate after unroll)
__device__ __forceinline__ void cp_wait(int n) {
    switch (n) {
        case 0: asm volatile("cp.async.wait_group 0;"); break;
        case 1: asm volatile("cp.async.wait_group 1;"); break;
        case 2: asm volatile("cp.async.wait_group 2;"); break;
        case 3: asm volatile("cp.async.wait_group 3;"); break;
        case 4: asm volatile("cp.async.wait_group 4;"); break;
        case 5: asm volatile("cp.async.wait_group 5;"); break;
        case 6: asm volatile("cp.async.wait_group 6;"); break;
        default: break;                          // 7: nothing older to wait on
    }
}
__device__ __forceinline__ int ld_acq(const volatile int* p) {
    int v; asm volatile("ld.acquire.gpu.b32 %0, [%1];" : "=r"(v) : "l"((const int*)p));
    return v;
}

// ---------------------------------------------------------------------------
// Kernel 0: per-(d,n) coefficients + flag clear
// ---------------------------------------------------------------------------
__global__ void coeff_kernel(const float* __restrict__ delta,
                             const float* __restrict__ alpha,
                             const float* __restrict__ beta,
                             const float* __restrict__ gamma) {
    int i = blockIdx.x * blockDim.x + threadIdx.x;
    if (i < NFLAGS) g_flag[i] = 0;
    if (i >= cD * cN) return;
    float p  = 1.f / (1.f + expf(-delta[i]));
    float a  = 1.f / (1.f + expf(-alpha[i]));
    float pa = p * a;
    g_q[i]  = 1.f - pa;
    g_cc[i] = p * beta[i] * gamma[i] * 0.25f;               // scale = sqrt(1/16)
    g_qS[i] = expf((float)cS * log1pf(-pa));                // q^S, accurate near q~1
}

// ---------------------------------------------------------------------------
// Fused kernel: load tile -> pass1 -> publish -> lookback -> pass2 (smem x)
// ---------------------------------------------------------------------------
__global__ void __launch_bounds__(TD, 3) fused_kernel(const float* __restrict__ x,
                                                      const float* __restrict__ omega,
                                                      float* __restrict__ out) {
    extern __shared__ float sx[];               // [cS][CHAN] = 64KB
    int d = blockIdx.x * CHAN + threadIdx.x;
    int c = blockIdx.y, b = blockIdx.z;

    const float* gbase = x + ((size_t)b * cL + (size_t)c * cS) * cD
                           + (size_t)blockIdx.x * CHAN;

    // ---- issue ALL stages up front (8 groups, 8KB each) ----
    {
        int base = threadIdx.x * 16;            // 16 floats per thread per stage
        int row = base >> 7;                    // /CHAN
        int col = base & (CHAN - 1);
#pragma unroll
        for (int st = 0; st < NSTAGES; st++) {
            int r = st * ST + row;
            u32 s = (u32)__cvta_generic_to_shared(sx + r * CHAN + col);
            const float* g = gbase + (size_t)r * cD + col;
            cp16(s, g);           cp16(s + 16, g + 4);
            cp16(s + 32, g + 8);  cp16(s + 48, g + 12);
            cp_commit();
        }
    }

    u64 q[8], h[8];
#pragma unroll
    for (int j = 0; j < 8; j++) {
        float2 v = *(const float2*)(g_q + d * cN + 2 * j);
        q[j] = pack2(v.x, v.y);
        h[j] = 0ULL;
    }

    // ---- pass 1: local end state (zero init), gated per stage ----
#pragma unroll
    for (int s = 0; s < NSTAGES; s++) {
        cp_wait(NSTAGES - 1 - s);
        __syncthreads();
        const float* sp = sx + s * ST * CHAN + threadIdx.x;
#pragma unroll
        for (int tt = 0; tt < ST; tt++) {
            float xv = sp[tt * CHAN];
            u64 a = pack2(xv, xv);
#pragma unroll
            for (int j = 0; j < 8; j++) h[j] = fma2(q[j], h[j], a);
        }
    }

    // ---- publish Le + flag ----
    size_t le_base = ((size_t)(b * cC + c) * cD + d) * cN;
#pragma unroll
    for (int j = 0; j < 8; j++)
        *(float2*)(g_Le + le_base + 2 * j) = unpack2(h[j]);
    int fbase = (b * cC) * NDBLK + blockIdx.x;
    __syncthreads();
    if (threadIdx.x == 0) {
        __threadfence();
        g_flag[fbase + c * NDBLK] = 1;
    }

    // ---- lookback: H0 = sum_{i<c} qS^{c-1-i} * Le[i] ----
#pragma unroll
    for (int j = 0; j < 8; j++) h[j] = 0ULL;
    if (c > 0) {
        // parallel wait for all predecessor flags
        for (int i = threadIdx.x; i < c; i += TD)
            while (ld_acq(&g_flag[fbase + i * NDBLK]) == 0)
                __nanosleep(64);
        __syncthreads();
        u64 qs[8], p[8];
#pragma unroll
        for (int j = 0; j < 8; j++) {
            float2 v = *(const float2*)(g_qS + d * cN + 2 * j);
            qs[j] = pack2(v.x, v.y);
            p[j] = pack2(1.f, 1.f);
        }
#pragma unroll 2
        for (int i = c - 1; i >= 0; i--) {
            size_t lb = ((size_t)(b * cC + i) * cD + d) * cN;
#pragma unroll
            for (int j = 0; j < 8; j++) {
                float2 le = *(const float2*)(g_Le + lb + 2 * j);
                h[j] = fma2(p[j], pack2(le.x, le.y), h[j]);
            }
            if (i > 0) {
#pragma unroll
                for (int j = 0; j < 8; j++) p[j] = mul2(p[j], qs[j]);
            }
        }
    }

    // ---- pass 2: outputs from smem x with correct prefix state ----
    u64 cc[8];
#pragma unroll
    for (int j = 0; j < 8; j++) {
        float2 cv = *(const float2*)(g_cc + d * cN + 2 * j);
        cc[j] = pack2(cv.x, cv.y);
    }
    float w = omega[d];
    float* op = out + ((size_t)b * cL + (size_t)c * cS) * cD + d;
    const float* sp = sx + threadIdx.x;
#pragma unroll 4
    for (int t = 0; t < cS; t++) {
        float xv = sp[t * CHAN];
        u64 a = pack2(xv, xv);
#pragma unroll
        for (int j = 0; j < 8; j++) h[j] = fma2(q[j], h[j], a);
        u64 s0 = mul2(cc[0], h[0]);
        u64 s1 = mul2(cc[1], h[1]);
        s0 = fma2(cc[2], h[2], s0);  s1 = fma2(cc[3], h[3], s1);
        s0 = fma2(cc[4], h[4], s0);  s1 = fma2(cc[5], h[5], s1);
        s0 = fma2(cc[6], h[6], s0);  s1 = fma2(cc[7], h[7], s1);
        float2 f = unpack2(add2(s0, s1));
        op[(size_t)t * cD] = fmaf(xv, w, f.x + f.y);
    }
}

// ---------------------------------------------------------------------------
extern "C" void kernel_launch(void* const* d_in, const int* in_sizes, int n_in,
                              void* d_out, int out_size) {
    const float* x     = (const float*)d_in[0];
    const float* delta = (const float*)d_in[1];
    const float* alpha = (const float*)d_in[2];
    const float* beta  = (const float*)d_in[3];
    const float* gamma = (const float*)d_in[4];
    const float* omega = (const float*)d_in[5];
    float* out = (float*)d_out;

    cudaFuncSetAttribute(fused_kernel,
                         cudaFuncAttributeMaxDynamicSharedMemorySize, SMEM_BYTES);
    coeff_kernel<<<(cD * cN + 255) / 256, 256>>>(delta, alpha, beta, gamma);
    dim3 grid(NDBLK, cC, cB);                   // (8, 32, 8) = 2048 CTAs
    fused_kernel<<<grid, TD, SMEM_BYTES>>>(x, omega, out);
}

// round 12
// speedup vs baseline: 1.1862x; 1.1862x over previous
#include <cuda_runtime.h>
#include <cstdint>

// MultiHeadEMA as a chunked diagonal linear recurrence (no FFT).
// out[b,t,d] = sum_n c[d,n] * h[d,n,t] + omega[d]*x[b,t,d]
// h[t] = q*h[t-1] + x[t],  q = 1 - sigmoid(delta)*sigmoid(alpha),
// c = sigmoid(delta)*beta*gamma*sqrt(1/N)
//
// R12: R10 skeleton (fused pass1 -> publish -> lookback -> pass2, C=16,
// TD=128, cp.async 3-stage pipeline) with: 8 CTAs/SM (reg cap 64),
// register-lean ascending lookback (no power array), parallel flag wait,
// pass2 stage-0/1 cp.async issued BEFORE the lookback, float4 Le I/O.

#define cB 8
#define cL 4096
#define cD 1024
#define cN 16
#define cC 16            // chunks
#define cS (cL / cC)     // 256 steps per chunk
#define TD 128           // threads per block (1 channel per thread)
#define ST 16            // timesteps per smem stage
#define NSTG 3           // pipeline stages
#define NSTAGE_ITERS (cS / ST)   // 16
#define NDBLK (cD / TD)  // 8
#define NFLAGS (cB * cC * NDBLK) // 1024

typedef unsigned long long u64;
typedef unsigned int u32;

// scratch (static __device__ arrays: no allocations allowed)
__device__ float g_q[cD * cN];
__device__ float g_cc[cD * cN];
__device__ float g_qS[cD * cN];
__device__ float g_Le[(size_t)cB * cC * cD * cN];  // local chunk end states
__device__ int g_flag[NFLAGS];                     // per (b,c,dblk) publish flag

__device__ __forceinline__ u64 pack2(float lo, float hi) {
    u64 r; asm("mov.b64 %0,{%1,%2};" : "=l"(r) : "f"(lo), "f"(hi)); return r;
}
__device__ __forceinline__ float2 unpack2(u64 v) {
    float2 f; asm("mov.b64 {%0,%1},%2;" : "=f"(f.x), "=f"(f.y) : "l"(v)); return f;
}
__device__ __forceinline__ u64 fma2(u64 a, u64 b, u64 c) {
    u64 d; asm("fma.rn.f32x2 %0,%1,%2,%3;" : "=l"(d) : "l"(a), "l"(b), "l"(c)); return d;
}
__device__ __forceinline__ u64 mul2(u64 a, u64 b) {
    u64 d; asm("mul.rn.f32x2 %0,%1,%2;" : "=l"(d) : "l"(a), "l"(b)); return d;
}
__device__ __forceinline__ u64 add2(u64 a, u64 b) {
    u64 d; asm("add.rn.f32x2 %0,%1,%2;" : "=l"(d) : "l"(a), "l"(b)); return d;
}
__device__ __forceinline__ void cp16(u32 saddr, const float* g) {
    asm volatile("cp.async.ca.shared.global [%0], [%1], 16;" :: "r"(saddr), "l"(g));
}
__device__ __forceinline__ void cp_commit() {
    asm volatile("cp.async.commit_group;");
}
__device__ __forceinline__ void cp_wait1() {
    asm volatile("cp.async.wait_group 1;");
}
__device__ __forceinline__ int ld_acq(const int* p) {
    int v; asm volatile("ld.acquire.gpu.b32 %0, [%1];" : "=r"(v) : "l"(p));
    return v;
}
__device__ __forceinline__ void st_rel(int* p, int v) {
    asm volatile("st.release.gpu.b32 [%0], %1;" :: "l"(p), "r"(v));
}

// Issue one stage's tile (ST x TD floats = 8KB) via cp.async; 4x16B/thread.
__device__ __forceinline__ void issue_stage(const float* gbase, int st,
                                            float* sbuf) {
    const float* g0 = gbase + (size_t)(st * ST) * cD;
    int col4 = (threadIdx.x & 31) * 4;
    int r0 = threadIdx.x >> 5;
#pragma unroll
    for (int k = 0; k < 4; k++) {
        int row = r0 + 4 * k;
        u32 s = (u32)__cvta_generic_to_shared(sbuf + row * TD + col4);
        cp16(s, g0 + (size_t)row * cD + col4);
    }
}

// ---------------------------------------------------------------------------
// Kernel 0: per-(d,n) coefficients + flag clear
// ---------------------------------------------------------------------------
__global__ void coeff_kernel(const float* __restrict__ delta,
                             const float* __restrict__ alpha,
                             const float* __restrict__ beta,
                             const float* __restrict__ gamma) {
    int i = blockIdx.x * blockDim.x + threadIdx.x;
    if (i < NFLAGS) g_flag[i] = 0;
    if (i >= cD * cN) return;
    float p  = 1.f / (1.f + expf(-delta[i]));
    float a  = 1.f / (1.f + expf(-alpha[i]));
    float pa = p * a;
    g_q[i]  = 1.f - pa;
    g_cc[i] = p * beta[i] * gamma[i] * 0.25f;               // scale = sqrt(1/16)
    g_qS[i] = expf((float)cS * log1pf(-pa));                // q^S, accurate near q~1
}

// ---------------------------------------------------------------------------
// Fused kernel: pass1 local states -> publish -> lookback -> pass2 outputs
// ---------------------------------------------------------------------------
__global__ void __launch_bounds__(TD, 8) fused_kernel(const float* __restrict__ x,
                                                      const float* __restrict__ omega,
                                                      float* __restrict__ out) {
    __shared__ float sx[NSTG][ST][TD];          // 24 KB
    int d = blockIdx.x * TD + threadIdx.x;
    int c = blockIdx.y, b = blockIdx.z;
    u64 q[8], h[8];
#pragma unroll
    for (int j = 0; j < 8; j++) {
        float2 v = *(const float2*)(g_q + d * cN + 2 * j);
        q[j] = pack2(v.x, v.y);
        h[j] = 0ULL;
    }
    const float* gbase = x + ((size_t)b * cL + (size_t)c * cS) * cD
                           + (size_t)blockIdx.x * TD;

    // ---- pass 1: local end state (zero init) ----
    issue_stage(gbase, 0, &sx[0][0][0]); cp_commit();
    issue_stage(gbase, 1, &sx[1][0][0]); cp_commit();
#pragma unroll 1
    for (int s = 0; s < NSTAGE_ITERS; s++) {
        cp_wait1();
        __syncthreads();
        if (s + 2 < NSTAGE_ITERS)
            issue_stage(gbase, s + 2, &sx[(s + 2) % NSTG][0][0]);
        cp_commit();                            // uniform group count
        const float* sp = &sx[s % NSTG][0][0] + threadIdx.x;
#pragma unroll
        for (int tt = 0; tt < ST; tt++) {
            float xv = sp[tt * TD];
            u64 a = pack2(xv, xv);
#pragma unroll
            for (int j = 0; j < 8; j++) h[j] = fma2(q[j], h[j], a);
        }
    }

    // ---- publish Le (float4 x2) + release flag ----
    size_t le_base = ((size_t)(b * cC + c) * cD + d) * cN;
    {
        float2 f0 = unpack2(h[0]), f1 = unpack2(h[1]);
        float2 f2 = unpack2(h[2]), f3 = unpack2(h[3]);
        *(float4*)(g_Le + le_base)     = make_float4(f0.x, f0.y, f1.x, f1.y);
        *(float4*)(g_Le + le_base + 4) = make_float4(f2.x, f2.y, f3.x, f3.y);
        f0 = unpack2(h[4]); f1 = unpack2(h[5]);
        f2 = unpack2(h[6]); f3 = unpack2(h[7]);
        *(float4*)(g_Le + le_base + 8)  = make_float4(f0.x, f0.y, f1.x, f1.y);
        *(float4*)(g_Le + le_base + 12) = make_float4(f2.x, f2.y, f3.x, f3.y);
    }
    int fbase = (b * cC) * NDBLK + blockIdx.x;
    __syncthreads();
    if (threadIdx.x == 0) {
        __threadfence();
        st_rel(&g_flag[fbase + c * NDBLK], 1);
    }

    // ---- start pass2's first loads now (overlap with lookback) ----
    __syncthreads();                            // pass1 smem consumed by all
    issue_stage(gbase, 0, &sx[0][0][0]); cp_commit();
    issue_stage(gbase, 1, &sx[1][0][0]); cp_commit();

    // ---- lookback: H0 = sum_{i<c} qS^{c-1-i} Le[i], ascending: H=qS*H+Le ----
#pragma unroll
    for (int j = 0; j < 8; j++) h[j] = 0ULL;
    if (c > 0) {
        for (int i = threadIdx.x; i < c; i += TD)
            while (ld_acq(&g_flag[fbase + i * NDBLK]) == 0)
                __nanosleep(32);
        __syncthreads();
        u64 qs[8];
#pragma unroll
        for (int j = 0; j < 8; j++) {
            float2 v = *(const float2*)(g_qS + d * cN + 2 * j);
            qs[j] = pack2(v.x, v.y);
        }
#pragma unroll 1
        for (int i = 0; i < c; i++) {
            const float4* lb = (const float4*)(g_Le +
                (((size_t)(b * cC + i) * cD + d) * cN));
#pragma unroll
            for (int k = 0; k < 4; k++) {
                float4 le = lb[k];
                h[2 * k]     = fma2(qs[2 * k],     h[2 * k],     pack2(le.x, le.y));
                h[2 * k + 1] = fma2(qs[2 * k + 1], h[2 * k + 1], pack2(le.z, le.w));
            }
        }
    }

    // ---- pass 2: outputs with correct prefix state ----
    u64 cc[8];
#pragma unroll
    for (int j = 0; j < 8; j++) {
        float2 cv = *(const float2*)(g_cc + d * cN + 2 * j);
        cc[j] = pack2(cv.x, cv.y);
    }
    float w = omega[d];
    float* op = out + ((size_t)b * cL + (size_t)c * cS) * cD + d;

#pragma unroll 1
    for (int s = 0; s < NSTAGE_ITERS; s++) {
        cp_wait1();
        __syncthreads();
        if (s + 2 < NSTAGE_ITERS)
            issue_stage(gbase, s + 2, &sx[(s + 2) % NSTG][0][0]);
        cp_commit();                            // uniform group count
        const float* sp = &sx[s % NSTG][0][0] + threadIdx.x;
#pragma unroll
        for (int tt = 0; tt < ST; tt++) {
            float xv = sp[tt * TD];
            u64 a = pack2(xv, xv);
#pragma unroll
            for (int j = 0; j < 8; j++) h[j] = fma2(q[j], h[j], a);
            u64 s0 = mul2(cc[0], h[0]);
            u64 s1 = mul2(cc[1], h[1]);
            s0 = fma2(cc[2], h[2], s0);  s1 = fma2(cc[3], h[3], s1);
            s0 = fma2(cc[4], h[4], s0);  s1 = fma2(cc[5], h[5], s1);
            s0 = fma2(cc[6], h[6], s0);  s1 = fma2(cc[7], h[7], s1);
            float2 f = unpack2(add2(s0, s1));
            op[(size_t)tt * cD] = fmaf(xv, w, f.x + f.y);
        }
        op += (size_t)ST * cD;
    }
}

// ---------------------------------------------------------------------------
extern "C" void kernel_launch(void* const* d_in, const int* in_sizes, int n_in,
                              void* d_out, int out_size) {
    const float* x     = (const float*)d_in[0];
    const float* delta = (const float*)d_in[1];
    const float* alpha = (const float*)d_in[2];
    const float* beta  = (const float*)d_in[3];
    const float* gamma = (const float*)d_in[4];
    const float* omega = (const float*)d_in[5];
    float* out = (float*)d_out;

    coeff_kernel<<<(cD * cN + 255) / 256, 256>>>(delta, alpha, beta, gamma);
    dim3 grid(NDBLK, cC, cB);                   // (8, 16, 8) = 1024 CTAs
    fused_kernel<<<grid, TD>>>(x, omega, out);
}

// round 13
// speedup vs baseline: 1.4283x; 1.2041x over previous
#include <cuda_runtime.h>
#include <cstdint>

// MultiHeadEMA as a chunked diagonal linear recurrence (no FFT).
// out[b,t,d] = sum_n c[d,n] * h[d,n,t] + omega[d]*x[b,t,d]
// h[t] = q*h[t-1] + x[t],  q = 1 - sigmoid(delta)*sigmoid(alpha),
// c = sigmoid(delta)*beta*gamma*sqrt(1/N)
//
// R13: R10 config (launch_bounds(128,7), no reg cap spills) + R12's cheap
// wins: float4 Le publish, parallel flag wait, ascending register-lean
// lookback (float4 loads), pass2 stage-0/1 cp.async issued before lookback.

#define cB 8
#define cL 4096
#define cD 1024
#define cN 16
#define cC 16            // chunks
#define cS (cL / cC)     // 256 steps per chunk
#define TD 128           // threads per block (1 channel per thread)
#define ST 16            // timesteps per smem stage
#define NSTG 3           // pipeline stages
#define NSTAGE_ITERS (cS / ST)   // 16
#define NDBLK (cD / TD)  // 8
#define NFLAGS (cB * cC * NDBLK) // 1024

typedef unsigned long long u64;
typedef unsigned int u32;

// scratch (static __device__ arrays: no allocations allowed)
__device__ float g_q[cD * cN];
__device__ float g_cc[cD * cN];
__device__ float g_qS[cD * cN];
__device__ float g_Le[(size_t)cB * cC * cD * cN];  // local chunk end states
__device__ int g_flag[NFLAGS];                     // per (b,c,dblk) publish flag

__device__ __forceinline__ u64 pack2(float lo, float hi) {
    u64 r; asm("mov.b64 %0,{%1,%2};" : "=l"(r) : "f"(lo), "f"(hi)); return r;
}
__device__ __forceinline__ float2 unpack2(u64 v) {
    float2 f; asm("mov.b64 {%0,%1},%2;" : "=f"(f.x), "=f"(f.y) : "l"(v)); return f;
}
__device__ __forceinline__ u64 fma2(u64 a, u64 b, u64 c) {
    u64 d; asm("fma.rn.f32x2 %0,%1,%2,%3;" : "=l"(d) : "l"(a), "l"(b), "l"(c)); return d;
}
__device__ __forceinline__ u64 mul2(u64 a, u64 b) {
    u64 d; asm("mul.rn.f32x2 %0,%1,%2;" : "=l"(d) : "l"(a), "l"(b)); return d;
}
__device__ __forceinline__ u64 add2(u64 a, u64 b) {
    u64 d; asm("add.rn.f32x2 %0,%1,%2;" : "=l"(d) : "l"(a), "l"(b)); return d;
}
__device__ __forceinline__ void cp16(u32 saddr, const float* g) {
    asm volatile("cp.async.ca.shared.global [%0], [%1], 16;" :: "r"(saddr), "l"(g));
}
__device__ __forceinline__ void cp_commit() {
    asm volatile("cp.async.commit_group;");
}
__device__ __forceinline__ void cp_wait1() {
    asm volatile("cp.async.wait_group 1;");
}
__device__ __forceinline__ int ld_acq(const int* p) {
    int v; asm volatile("ld.acquire.gpu.b32 %0, [%1];" : "=r"(v) : "l"(p));
    return v;
}
__device__ __forceinline__ void st_rel(int* p, int v) {
    asm volatile("st.release.gpu.b32 [%0], %1;" :: "l"(p), "r"(v));
}

// Issue one stage's tile (ST x TD floats = 8KB) via cp.async; 4x16B/thread.
__device__ __forceinline__ void issue_stage(const float* gbase, int st,
                                            float* sbuf) {
    const float* g0 = gbase + (size_t)(st * ST) * cD;
    int col4 = (threadIdx.x & 31) * 4;
    int r0 = threadIdx.x >> 5;
#pragma unroll
    for (int k = 0; k < 4; k++) {
        int row = r0 + 4 * k;
        u32 s = (u32)__cvta_generic_to_shared(sbuf + row * TD + col4);
        cp16(s, g0 + (size_t)row * cD + col4);
    }
}

// ---------------------------------------------------------------------------
// Kernel 0: per-(d,n) coefficients + flag clear
// ---------------------------------------------------------------------------
__global__ void coeff_kernel(const float* __restrict__ delta,
                             const float* __restrict__ alpha,
                             const float* __restrict__ beta,
                             const float* __restrict__ gamma) {
    int i = blockIdx.x * blockDim.x + threadIdx.x;
    if (i < NFLAGS) g_flag[i] = 0;
    if (i >= cD * cN) return;
    float p  = 1.f / (1.f + expf(-delta[i]));
    float a  = 1.f / (1.f + expf(-alpha[i]));
    float pa = p * a;
    g_q[i]  = 1.f - pa;
    g_cc[i] = p * beta[i] * gamma[i] * 0.25f;               // scale = sqrt(1/16)
    g_qS[i] = expf((float)cS * log1pf(-pa));                // q^S, accurate near q~1
}

// ---------------------------------------------------------------------------
// Fused kernel: pass1 local states -> publish -> lookback -> pass2 outputs
// ---------------------------------------------------------------------------
__global__ void __launch_bounds__(TD, 7) fused_kernel(const float* __restrict__ x,
                                                      const float* __restrict__ omega,
                                                      float* __restrict__ out) {
    __shared__ float sx[NSTG][ST][TD];          // 24 KB
    int d = blockIdx.x * TD + threadIdx.x;
    int c = blockIdx.y, b = blockIdx.z;
    u64 q[8], h[8];
#pragma unroll
    for (int j = 0; j < 8; j++) {
        float2 v = *(const float2*)(g_q + d * cN + 2 * j);
        q[j] = pack2(v.x, v.y);
        h[j] = 0ULL;
    }
    const float* gbase = x + ((size_t)b * cL + (size_t)c * cS) * cD
                           + (size_t)blockIdx.x * TD;

    // ---- pass 1: local end state (zero init) ----
    issue_stage(gbase, 0, &sx[0][0][0]); cp_commit();
    issue_stage(gbase, 1, &sx[1][0][0]); cp_commit();
#pragma unroll 1
    for (int s = 0; s < NSTAGE_ITERS; s++) {
        cp_wait1();
        __syncthreads();
        if (s + 2 < NSTAGE_ITERS)
            issue_stage(gbase, s + 2, &sx[(s + 2) % NSTG][0][0]);
        cp_commit();                            // uniform group count
        const float* sp = &sx[s % NSTG][0][0] + threadIdx.x;
#pragma unroll
        for (int tt = 0; tt < ST; tt++) {
            float xv = sp[tt * TD];
            u64 a = pack2(xv, xv);
#pragma unroll
            for (int j = 0; j < 8; j++) h[j] = fma2(q[j], h[j], a);
        }
    }

    // ---- publish Le (float4 x4) + release flag ----
    size_t le_base = ((size_t)(b * cC + c) * cD + d) * cN;
    {
        float2 f0 = unpack2(h[0]), f1 = unpack2(h[1]);
        float2 f2 = unpack2(h[2]), f3 = unpack2(h[3]);
        *(float4*)(g_Le + le_base)     = make_float4(f0.x, f0.y, f1.x, f1.y);
        *(float4*)(g_Le + le_base + 4) = make_float4(f2.x, f2.y, f3.x, f3.y);
        f0 = unpack2(h[4]); f1 = unpack2(h[5]);
        f2 = unpack2(h[6]); f3 = unpack2(h[7]);
        *(float4*)(g_Le + le_base + 8)  = make_float4(f0.x, f0.y, f1.x, f1.y);
        *(float4*)(g_Le + le_base + 12) = make_float4(f2.x, f2.y, f3.x, f3.y);
    }
    int fbase = (b * cC) * NDBLK + blockIdx.x;
    __syncthreads();
    if (threadIdx.x == 0) {
        __threadfence();
        st_rel(&g_flag[fbase + c * NDBLK], 1);
    }

    // ---- start pass2's first loads now (overlap with lookback) ----
    __syncthreads();                            // pass1 smem fully consumed
    issue_stage(gbase, 0, &sx[0][0][0]); cp_commit();
    issue_stage(gbase, 1, &sx[1][0][0]); cp_commit();

    // ---- lookback: H0 = sum_{i<c} qS^{c-1-i} Le[i], ascending: H=qS*H+Le ----
#pragma unroll
    for (int j = 0; j < 8; j++) h[j] = 0ULL;
    if (c > 0) {
        for (int i = threadIdx.x; i < c; i += TD)
            while (ld_acq(&g_flag[fbase + i * NDBLK]) == 0)
                __nanosleep(32);
        __syncthreads();
        u64 qs[8];
#pragma unroll
        for (int j = 0; j < 8; j++) {
            float2 v = *(const float2*)(g_qS + d * cN + 2 * j);
            qs[j] = pack2(v.x, v.y);
        }
#pragma unroll 1
        for (int i = 0; i < c; i++) {
            const float4* lb = (const float4*)(g_Le +
                (((size_t)(b * cC + i) * cD + d) * cN));
#pragma unroll
            for (int k = 0; k < 4; k++) {
                float4 le = lb[k];
                h[2 * k]     = fma2(qs[2 * k],     h[2 * k],     pack2(le.x, le.y));
                h[2 * k + 1] = fma2(qs[2 * k + 1], h[2 * k + 1], pack2(le.z, le.w));
            }
        }
    }

    // ---- pass 2: outputs with correct prefix state ----
    u64 cc[8];
#pragma unroll
    for (int j = 0; j < 8; j++) {
        float2 cv = *(const float2*)(g_cc + d * cN + 2 * j);
        cc[j] = pack2(cv.x, cv.y);
    }
    float w = omega[d];
    float* op = out + ((size_t)b * cL + (size_t)c * cS) * cD + d;

#pragma unroll 1
    for (int s = 0; s < NSTAGE_ITERS; s++) {
        cp_wait1();
        __syncthreads();
        if (s + 2 < NSTAGE_ITERS)
            issue_stage(gbase, s + 2, &sx[(s + 2) % NSTG][0][0]);
        cp_commit();                            // uniform group count
        const float* sp = &sx[s % NSTG][0][0] + threadIdx.x;
#pragma unroll
        for (int tt = 0; tt < ST; tt++) {
            float xv = sp[tt * TD];
            u64 a = pack2(xv, xv);
#pragma unroll
            for (int j = 0; j < 8; j++) h[j] = fma2(q[j], h[j], a);
            u64 s0 = mul2(cc[0], h[0]);
            u64 s1 = mul2(cc[1], h[1]);
            s0 = fma2(cc[2], h[2], s0);  s1 = fma2(cc[3], h[3], s1);
            s0 = fma2(cc[4], h[4], s0);  s1 = fma2(cc[5], h[5], s1);
            s0 = fma2(cc[6], h[6], s0);  s1 = fma2(cc[7], h[7], s1);
            float2 f = unpack2(add2(s0, s1));
            op[(size_t)tt * cD] = fmaf(xv, w, f.x + f.y);
        }
        op += (size_t)ST * cD;
    }
}

// ---------------------------------------------------------------------------
extern "C" void kernel_launch(void* const* d_in, const int* in_sizes, int n_in,
                              void* d_out, int out_size) {
    const float* x     = (const float*)d_in[0];
    const float* delta = (const float*)d_in[1];
    const float* alpha = (const float*)d_in[2];
    const float* beta  = (const float*)d_in[3];
    const float* gamma = (const float*)d_in[4];
    const float* omega = (const float*)d_in[5];
    float* out = (float*)d_out;

    coeff_kernel<<<(cD * cN + 255) / 256, 256>>>(delta, alpha, beta, gamma);
    dim3 grid(NDBLK, cC, cB);                   // (8, 16, 8) = 1024 CTAs
    fused_kernel<<<grid, TD>>>(x, omega, out);
}